// round 14
// baseline (speedup 1.0000x reference)
#include <cuda_runtime.h>
#include <cuda_bf16.h>
#include <cuda_fp16.h>
#include <cstdint>

#define BB 32
#define SS 4096
#define DD 64
#define KCC 256

// ------------------------- device global scratch ---------------------------
__device__ __half g_Wh[2 * KCC * SS];        // [proj][kc][s] fp16
__device__ float  g_acc[2 * BB * KCC * DD];  // [proj][b][kc][d] fp32 partials
__device__ __nv_bfloat16 g_Keh[BB * KCC * DD];   // [b][kc][d] bf16 hi
__device__ __nv_bfloat16 g_Kel[BB * KCC * DD];   // lo
__device__ __nv_bfloat16 g_Vfh[BB * KCC * DD];   // hi
__device__ __nv_bfloat16 g_Vfl[BB * KCC * DD];   // lo

// ------------------------------ helpers ------------------------------------
__device__ __forceinline__ uint32_t smem_u32(const void* p) {
    uint32_t a;
    asm("{ .reg .u64 t; cvta.to.shared.u64 t, %1; cvt.u32.u64 %0, t; }"
        : "=r"(a) : "l"(p));
    return a;
}
#define SW128(x) ((x) ^ (((x) >> 3) & 0x70))

__device__ __forceinline__ void cp16(uint32_t dst, const void* src) {
    asm volatile("cp.async.cg.shared.global [%0], [%1], 16;"
                 :: "r"(dst), "l"(src) : "memory");
}
__device__ __forceinline__ void cp_commit() {
    asm volatile("cp.async.commit_group;" ::: "memory");
}
template <int N>
__device__ __forceinline__ void cp_wait() {
    asm volatile("cp.async.wait_group %0;" :: "n"(N) : "memory");
}
__device__ __forceinline__ void ldm_x4(uint32_t* r, uint32_t addr) {
    asm volatile("ldmatrix.sync.aligned.m8n8.x4.shared.b16 {%0,%1,%2,%3}, [%4];"
                 : "=r"(r[0]), "=r"(r[1]), "=r"(r[2]), "=r"(r[3]) : "r"(addr));
}
__device__ __forceinline__ void ldm_x4_t(uint32_t* r, uint32_t addr) {
    asm volatile("ldmatrix.sync.aligned.m8n8.x4.trans.shared.b16 {%0,%1,%2,%3}, [%4];"
                 : "=r"(r[0]), "=r"(r[1]), "=r"(r[2]), "=r"(r[3]) : "r"(addr));
}
__device__ __forceinline__ void mma_bf16(
    float* c, const uint32_t* a, uint32_t b0, uint32_t b1) {
    asm volatile(
        "mma.sync.aligned.m16n8k16.row.col.f32.bf16.bf16.f32 "
        "{%0,%1,%2,%3}, {%4,%5,%6,%7}, {%8,%9}, {%0,%1,%2,%3};"
        : "+f"(c[0]), "+f"(c[1]), "+f"(c[2]), "+f"(c[3])
        : "r"(a[0]), "r"(a[1]), "r"(a[2]), "r"(a[3]), "r"(b0), "r"(b1));
}
__device__ __forceinline__ void mma_f16(
    float* c, const uint32_t* a, uint32_t b0, uint32_t b1) {
    asm volatile(
        "mma.sync.aligned.m16n8k16.row.col.f32.f16.f16.f32 "
        "{%0,%1,%2,%3}, {%4,%5,%6,%7}, {%8,%9}, {%0,%1,%2,%3};"
        : "+f"(c[0]), "+f"(c[1]), "+f"(c[2]), "+f"(c[3])
        : "r"(a[0]), "r"(a[1]), "r"(a[2]), "r"(a[3]), "r"(b0), "r"(b1));
}
__device__ __forceinline__ uint32_t packbf(float lo, float hi) {
    uint32_t r;
    asm("cvt.rn.bf16x2.f32 %0, %1, %2;" : "=r"(r) : "f"(hi), "f"(lo));
    return r;
}
__device__ __forceinline__ uint32_t packhf(float lo, float hi) {
    uint32_t r;
    asm("cvt.rn.f16x2.f32 %0, %1, %2;" : "=r"(r) : "f"(hi), "f"(lo));
    return r;
}
__device__ __forceinline__ float bfres(float v) {   // v - bf16(v)
    return v - __bfloat162float(__float2bfloat16(v));
}

// ---------------------------------------------------------------------------
// conv_w: E_w / F_w (fp32 [256][4096]) -> fp16, same layout. Grid (1024, 2).
// ---------------------------------------------------------------------------
__global__ __launch_bounds__(256) void conv_w_kernel(
    const float* __restrict__ Ew, const float* __restrict__ Fw)
{
    const int y = blockIdx.y;
    const float4* src = reinterpret_cast<const float4*>(y ? Fw : Ew);
    const int i = blockIdx.x * 256 + threadIdx.x;
    float4 v = src[i];
    __half2* oh = reinterpret_cast<__half2*>(g_Wh + (size_t)y * KCC * SS) + 2 * i;
    oh[0] = __halves2half2(__float2half(v.x), __float2half(v.y));
    oh[1] = __halves2half2(__float2half(v.z), __float2half(v.w));
}

// ---------------------------------------------------------------------------
// proj_mma: mma.sync fp16 GEMM; s-quarter split + 2 batches per CTA.
// Grid (4, 16, 2) = 128 CTAs. Block 256. Same as R13 except float2 atomics.
// SMEM: W 3x32KB @0 | Xf 3x32KB @98304 | Xh 2x16KB @196608 = 224 KB.
// ---------------------------------------------------------------------------
__global__ __launch_bounds__(256) void proj_mma_kernel(
    const float* __restrict__ Kf, const float* __restrict__ Vf)
{
    extern __shared__ char sm[];
    const uint32_t smb = smem_u32(sm);
    const int tid = threadIdx.x, wid = tid >> 5, lane = tid & 31;
    const int sq = blockIdx.x, bp = blockIdx.y, proj = blockIdx.z;
    const int mw = wid >> 2, nw = wid & 3;
    const int g = lane >> 2, q = lane & 3;

    const __half* Wh = g_Wh + (size_t)proj * KCC * SS;
    const float* Xsrc = proj ? Vf : Kf;
    const float* Xb[2] = { Xsrc + (size_t)(2 * bp) * SS * DD,
                           Xsrc + (size_t)(2 * bp + 1) * SS * DD };
    const int sbase = sq * 1024;

    float acc[2][8][2][4];
#pragma unroll
    for (int bb = 0; bb < 2; bb++)
#pragma unroll
        for (int mf = 0; mf < 8; mf++)
#pragma unroll
            for (int nf = 0; nf < 2; nf++)
#pragma unroll
                for (int i = 0; i < 4; i++) acc[bb][mf][nf][i] = 0.f;

    const int NC = 1024 / 64;   // 16 chunks

    auto load_chunk = [&](int c) {
        const uint32_t wbuf = smb + (c % 3) * 32768;
#pragma unroll
        for (int idx = tid; idx < 2048; idx += 256) {
            int row = idx >> 3, s16 = idx & 7;
            size_t so = (size_t)row * SS + sbase + c * 64 + s16 * 8;
            uint32_t bo = SW128((uint32_t)(row * 128 + s16 * 16));
            cp16(wbuf + bo, Wh + so);
        }
        const uint32_t xfbuf = smb + 98304 + (c % 3) * 32768;
#pragma unroll
        for (int bb = 0; bb < 2; bb++) {
            const float* xsrc = Xb[bb] + (size_t)(sbase + c * 64) * DD;
#pragma unroll
            for (int u = 0; u < 2; u++) {
                int seg = tid + u * 256;
                cp16(xfbuf + bb * 16384 + seg * 32,      xsrc + seg * 8);
                cp16(xfbuf + bb * 16384 + seg * 32 + 16, xsrc + seg * 8 + 4);
            }
        }
        cp_commit();
    };

    auto convert_x = [&](int c) {
        const char* xf = sm + 98304 + (c % 3) * 32768;
        char* xbb = sm + 196608 + (c & 1) * 16384;
#pragma unroll
        for (int bb = 0; bb < 2; bb++)
#pragma unroll
            for (int u = 0; u < 2; u++) {
                int seg = tid + u * 256;
                int row = seg >> 3, s16 = seg & 7;
                float4 v0 = *reinterpret_cast<const float4*>(
                    xf + bb * 16384 + seg * 32);
                float4 v1 = *reinterpret_cast<const float4*>(
                    xf + bb * 16384 + seg * 32 + 16);
                uint32_t bo = SW128((uint32_t)(row * 128 + s16 * 16));
                uint4 h;
                h.x = packhf(v0.x, v0.y); h.y = packhf(v0.z, v0.w);
                h.z = packhf(v1.x, v1.y); h.w = packhf(v1.z, v1.w);
                *reinterpret_cast<uint4*>(xbb + bb * 8192 + bo) = h;
            }
    };

    load_chunk(0); load_chunk(1);

    for (int c = 0; c < NC; c++) {
        if (c + 2 < NC) { load_chunk(c + 2); cp_wait<2>(); }
        else            { cp_wait<0>(); }

        convert_x(c);
        __syncthreads();

        const uint32_t Ah = smb + (c % 3) * 32768;
        const uint32_t Xh = smb + 196608 + (c & 1) * 16384;
        const int lr = lane & 15, lc = (lane >> 4) * 16;

#pragma unroll
        for (int kk = 0; kk < 4; kk++) {
            uint32_t bh[2][4];
            uint32_t boff = SW128((uint32_t)((kk * 16 + lr) * 128 + nw * 32 + lc));
            ldm_x4_t(bh[0], Xh + boff);
            ldm_x4_t(bh[1], Xh + 8192 + boff);
#pragma unroll
            for (int mf = 0; mf < 8; mf++) {
                uint32_t ah[4];
                uint32_t off = SW128((uint32_t)(
                    (mw * 128 + mf * 16 + lr) * 128 + kk * 32 + lc));
                ldm_x4(ah, Ah + off);
#pragma unroll
                for (int bb = 0; bb < 2; bb++)
#pragma unroll
                    for (int nf = 0; nf < 2; nf++)
                        mma_f16(acc[bb][mf][nf], ah,
                                bh[bb][2 * nf], bh[bb][2 * nf + 1]);
            }
        }
        __syncthreads();
    }

    // ---- epilogue: vector float2 atomics into g_acc ----
#pragma unroll
    for (int bb = 0; bb < 2; bb++) {
        float* out = g_acc + ((size_t)proj * BB + 2 * bp + bb) * KCC * DD;
#pragma unroll
        for (int mf = 0; mf < 8; mf++) {
            const int kcl = mw * 128 + mf * 16 + g;
#pragma unroll
            for (int nf = 0; nf < 2; nf++) {
                const int d0 = nw * 16 + nf * 8 + 2 * q;
                atomicAdd(reinterpret_cast<float2*>(&out[(size_t)kcl * DD + d0]),
                          make_float2(acc[bb][mf][nf][0], acc[bb][mf][nf][1]));
                atomicAdd(reinterpret_cast<float2*>(&out[(size_t)(kcl + 8) * DD + d0]),
                          make_float2(acc[bb][mf][nf][2], acc[bb][mf][nf][3]));
            }
        }
    }
}

// ---------------------------------------------------------------------------
// finalize: g_acc (+bias) -> bf16 hi/lo arrays, ONCE per element.
// Grid (BB*4, 2). Block 256; each block does a quarter of one (b, proj).
// ---------------------------------------------------------------------------
__global__ __launch_bounds__(256) void finalize_kernel(
    const float* __restrict__ E_b, const float* __restrict__ F_b)
{
    const int blk = blockIdx.x, proj = blockIdx.y;
    const int b = blk >> 2, quarter = blk & 3;
    const float* src = g_acc + ((size_t)proj * BB + b) * KCC * DD;
    const float* bias = proj ? F_b : E_b;
    __nv_bfloat16* oh = (proj ? g_Vfh : g_Keh) + (size_t)b * KCC * DD;
    __nv_bfloat16* ol = (proj ? g_Vfl : g_Kel) + (size_t)b * KCC * DD;

    const int i0 = quarter * 1024;          // float4 index base (4096 total)
#pragma unroll
    for (int t = 0; t < 4; t++) {
        const int i = i0 + t * 256 + threadIdx.x;
        const int kc = (i * 4) >> 6;        // float4 never crosses kc boundary
        const float bv = bias[kc];
        float4 v = reinterpret_cast<const float4*>(src)[i];
        v.x += bv; v.y += bv; v.z += bv; v.w += bv;
        uint2 h, l;
        h.x = packbf(v.x, v.y); h.y = packbf(v.z, v.w);
        l.x = packbf(bfres(v.x), bfres(v.y));
        l.y = packbf(bfres(v.z), bfres(v.w));
        reinterpret_cast<uint2*>(oh)[i] = h;
        reinterpret_cast<uint2*>(ol)[i] = l;
    }
}

// ---------------------------------------------------------------------------
// attn: tensor-core fused attention (rows 0..255) + fused broadcast.
// Grid (4, B). Block 256: warps 0-3 do MMA (16 rows each); warps 4-7 assist
// loads, Q conversion, and the broadcast phase.
// SMEM: Ke h/l 64K | Vf h/l 64K | Q h/l 16K = 144KB.
// ---------------------------------------------------------------------------
__global__ __launch_bounds__(256) void attn_kernel(
    const float* __restrict__ Qf, float* __restrict__ out)
{
    extern __shared__ char sm[];
    const uint32_t smb = smem_u32(sm);
    const uint32_t KEH = 0, KEL = 32768, VFH = 65536, VFL = 98304,
                   QH = 131072, QL = 139264;

    const int tid = threadIdx.x, lane = tid & 31, warp = tid >> 5;
    const int b = blockIdx.y;
    const int s0 = blockIdx.x * 64;
    const int g = lane >> 2, q = lane & 3;
    const int lr = lane & 15, lcb = (lane >> 4) * 16;

    // ---- Ke / Vf bf16 tiles via cp.async (256 threads) ----
    {
        const __nv_bfloat16* keh = g_Keh + (size_t)b * KCC * DD;
        const __nv_bfloat16* kel = g_Kel + (size_t)b * KCC * DD;
        const __nv_bfloat16* vfh = g_Vfh + (size_t)b * KCC * DD;
        const __nv_bfloat16* vfl = g_Vfl + (size_t)b * KCC * DD;
#pragma unroll
        for (int idx = tid; idx < 2048; idx += 256) {
            int row = idx >> 3, seg = idx & 7;
            size_t so = (size_t)row * DD + seg * 8;
            uint32_t bo = SW128((uint32_t)(row * 128 + seg * 16));
            cp16(smb + KEH + bo, keh + so);
            cp16(smb + KEL + bo, kel + so);
            cp16(smb + VFH + bo, vfh + so);
            cp16(smb + VFL + bo, vfl + so);
        }
        cp_commit();
    }
    // ---- Q: fp32 -> bf16 hi/lo smem (256 threads) ----
    {
        const float* qb = Qf + ((size_t)b * SS + s0) * DD;
#pragma unroll
        for (int idx = tid; idx < 512; idx += 256) {
            int row = idx >> 3, seg = idx & 7;
            const float* qp = qb + (size_t)row * DD + seg * 8;
            float4 v0 = *reinterpret_cast<const float4*>(qp);
            float4 v1 = *reinterpret_cast<const float4*>(qp + 4);
            uint32_t bo = SW128((uint32_t)(row * 128 + seg * 16));
            uint4 h, l;
            h.x = packbf(v0.x, v0.y); h.y = packbf(v0.z, v0.w);
            h.z = packbf(v1.x, v1.y); h.w = packbf(v1.z, v1.w);
            l.x = packbf(bfres(v0.x), bfres(v0.y));
            l.y = packbf(bfres(v0.z), bfres(v0.w));
            l.z = packbf(bfres(v1.x), bfres(v1.y));
            l.w = packbf(bfres(v1.z), bfres(v1.w));
            *reinterpret_cast<uint4*>(sm + QH + bo) = h;
            *reinterpret_cast<uint4*>(sm + QL + bo) = l;
        }
        cp_wait<0>();
        __syncthreads();
    }

    if (warp < 4) {
        const int j0 = blockIdx.x * 4 + warp;   // first unmasked kc tile

        float acc[32][4];
#pragma unroll
        for (int nf = 0; nf < 32; nf++)
#pragma unroll
            for (int i = 0; i < 4; i++) acc[nf][i] = 0.f;

#pragma unroll
        for (int kk = 0; kk < 4; kk++) {
            uint32_t qh[4], ql[4];
            uint32_t offA = SW128((uint32_t)((warp * 16 + lr) * 128 + kk * 32 + lcb));
            ldm_x4(qh, smb + QH + offA);
            ldm_x4(ql, smb + QL + offA);
#pragma unroll
            for (int j = 0; j < 16; j++) {
                if (j >= j0) {
                    uint32_t off = SW128((uint32_t)((j * 16 + lr) * 128 + kk * 32 + lcb));
                    uint32_t bh[4], bl[4];
                    ldm_x4(bh, smb + KEH + off);
                    ldm_x4(bl, smb + KEL + off);
                    mma_bf16(acc[2 * j],     qh, bh[0], bh[2]);
                    mma_bf16(acc[2 * j],     ql, bh[0], bh[2]);
                    mma_bf16(acc[2 * j],     qh, bl[0], bl[2]);
                    mma_bf16(acc[2 * j + 1], qh, bh[1], bh[3]);
                    mma_bf16(acc[2 * j + 1], ql, bh[1], bh[3]);
                    mma_bf16(acc[2 * j + 1], qh, bl[1], bl[3]);
                }
            }
        }

        const int rowa = s0 + warp * 16 + g;
        const int rowb = rowa + 8;
        float mxa = -3.4e38f, mxb = -3.4e38f;
#pragma unroll
        for (int nf = 0; nf < 32; nf++) {
            const int kc = 8 * nf + 2 * q;
            acc[nf][0] = (kc     >= rowa) ? acc[nf][0] * 0.125f : -1e10f;
            acc[nf][1] = (kc + 1 >= rowa) ? acc[nf][1] * 0.125f : -1e10f;
            acc[nf][2] = (kc     >= rowb) ? acc[nf][2] * 0.125f : -1e10f;
            acc[nf][3] = (kc + 1 >= rowb) ? acc[nf][3] * 0.125f : -1e10f;
            mxa = fmaxf(mxa, fmaxf(acc[nf][0], acc[nf][1]));
            mxb = fmaxf(mxb, fmaxf(acc[nf][2], acc[nf][3]));
        }
#pragma unroll
        for (int o = 1; o <= 2; o <<= 1) {
            mxa = fmaxf(mxa, __shfl_xor_sync(0xffffffffu, mxa, o));
            mxb = fmaxf(mxb, __shfl_xor_sync(0xffffffffu, mxb, o));
        }
        float sa = 0.f, sb = 0.f;
#pragma unroll
        for (int nf = 0; nf < 32; nf++) {
            acc[nf][0] = __expf(acc[nf][0] - mxa);
            acc[nf][1] = __expf(acc[nf][1] - mxa);
            acc[nf][2] = __expf(acc[nf][2] - mxb);
            acc[nf][3] = __expf(acc[nf][3] - mxb);
            sa += acc[nf][0] + acc[nf][1];
            sb += acc[nf][2] + acc[nf][3];
        }
#pragma unroll
        for (int o = 1; o <= 2; o <<= 1) {
            sa += __shfl_xor_sync(0xffffffffu, sa, o);
            sb += __shfl_xor_sync(0xffffffffu, sb, o);
        }
        const float inva = 1.f / sa, invb = 1.f / sb;

        uint32_t pAh[32], pAl[32], pBh[32], pBl[32];
#pragma unroll
        for (int nf = 0; nf < 32; nf++) {
            float p0 = acc[nf][0] * inva, p1 = acc[nf][1] * inva;
            float p2 = acc[nf][2] * invb, p3 = acc[nf][3] * invb;
            pAh[nf] = packbf(p0, p1);
            pBh[nf] = packbf(p2, p3);
            pAl[nf] = packbf(bfres(p0), bfres(p1));
            pBl[nf] = packbf(bfres(p2), bfres(p3));
        }

        float acc2[8][4];
#pragma unroll
        for (int u = 0; u < 8; u++)
#pragma unroll
            for (int i = 0; i < 4; i++) acc2[u][i] = 0.f;

#pragma unroll
        for (int ks = 0; ks < 16; ks++) {
            if (ks >= j0) {
                uint32_t a_h[4] = {pAh[2 * ks], pBh[2 * ks],
                                   pAh[2 * ks + 1], pBh[2 * ks + 1]};
                uint32_t a_l[4] = {pAl[2 * ks], pBl[2 * ks],
                                   pAl[2 * ks + 1], pBl[2 * ks + 1]};
#pragma unroll
                for (int t = 0; t < 4; t++) {
                    uint32_t off = SW128((uint32_t)((ks * 16 + lr) * 128 + t * 32 + lcb));
                    uint32_t vh[4], vl[4];
                    ldm_x4_t(vh, smb + VFH + off);
                    ldm_x4_t(vl, smb + VFL + off);
                    mma_bf16(acc2[2 * t],     a_h, vh[0], vh[1]);
                    mma_bf16(acc2[2 * t],     a_l, vh[0], vh[1]);
                    mma_bf16(acc2[2 * t],     a_h, vl[0], vl[1]);
                    mma_bf16(acc2[2 * t + 1], a_h, vh[2], vh[3]);
                    mma_bf16(acc2[2 * t + 1], a_l, vh[2], vh[3]);
                    mma_bf16(acc2[2 * t + 1], a_h, vl[2], vl[3]);
                }
            }
        }

        float* ob = out + (size_t)b * SS * DD;
#pragma unroll
        for (int u = 0; u < 8; u++) {
            const int d0 = 8 * u + 2 * q;
            *reinterpret_cast<float2*>(&ob[(size_t)rowa * DD + d0]) =
                make_float2(acc2[u][0], acc2[u][1]);
            *reinterpret_cast<float2*>(&ob[(size_t)rowb * DD + d0]) =
                make_float2(acc2[u][2], acc2[u][3]);
        }
    }

    // ---- fused broadcast (all 8 warps): rows >= KC get mean_k Vf[k][:]. ----
    __syncthreads();
    {
        float* red = reinterpret_cast<float*>(sm + QH);          // [8][64]
        float* meanv = reinterpret_cast<float*>(sm + QH) + 512;  // [64]
        const int dp = tid & 31, kq = tid >> 5;                  // 8 k-groups
        float m0 = 0.f, m1 = 0.f;
        for (int k = kq * 32; k < kq * 32 + 32; k++) {
            uint32_t off = SW128((uint32_t)(k * 128 + dp * 4));
            uint32_t hw = *reinterpret_cast<const uint32_t*>(sm + VFH + off);
            uint32_t lw = *reinterpret_cast<const uint32_t*>(sm + VFL + off);
            __nv_bfloat162 hv = *reinterpret_cast<__nv_bfloat162*>(&hw);
            __nv_bfloat162 lv = *reinterpret_cast<__nv_bfloat162*>(&lw);
            m0 += __bfloat162float(hv.x) + __bfloat162float(lv.x);
            m1 += __bfloat162float(hv.y) + __bfloat162float(lv.y);
        }
        red[kq * 64 + 2 * dp]     = m0;
        red[kq * 64 + 2 * dp + 1] = m1;
        __syncthreads();
        if (tid < 64) {
            float t = 0.f;
#pragma unroll
            for (int k = 0; k < 8; k++) t += red[k * 64 + tid];
            meanv[tid] = t * (1.f / 256.f);
        }
        __syncthreads();

        const int ccol = tid & 15, rofs = tid >> 4;              // 16 row-lanes
        const float4 val = make_float4(meanv[ccol * 4], meanv[ccol * 4 + 1],
                                       meanv[ccol * 4 + 2], meanv[ccol * 4 + 3]);
        float4* obv = reinterpret_cast<float4*>(out + (size_t)b * SS * DD);
        const int r0b = KCC + blockIdx.x * 960;
#pragma unroll 4
        for (int r = r0b + rofs; r < r0b + 960; r += 16)
            obv[(size_t)r * 16 + ccol] = val;
    }
}

// ---------------------------------------------------------------------------
// Harness entry. Inputs: Q, K, V, E_w, E_b, F_w, F_b. Output f32 [B,S,D].
// ---------------------------------------------------------------------------
extern "C" void kernel_launch(void* const* d_in, const int* in_sizes, int n_in,
                              void* d_out, int out_size)
{
    (void)in_sizes; (void)n_in; (void)out_size;
    const float* Q   = (const float*)d_in[0];
    const float* K   = (const float*)d_in[1];
    const float* V   = (const float*)d_in[2];
    const float* E_w = (const float*)d_in[3];
    const float* E_b = (const float*)d_in[4];
    const float* F_w = (const float*)d_in[5];
    const float* F_b = (const float*)d_in[6];
    float* out = (float*)d_out;

    const int proj_smem = 229376;   // 224 KB
    const int attn_smem = 147456;   // 144 KB
    cudaFuncSetAttribute(proj_mma_kernel,
                         cudaFuncAttributeMaxDynamicSharedMemorySize, proj_smem);
    cudaFuncSetAttribute(attn_kernel,
                         cudaFuncAttributeMaxDynamicSharedMemorySize, attn_smem);

    void* accptr = nullptr;
    cudaGetSymbolAddress(&accptr, g_acc);
    cudaMemsetAsync(accptr, 0, sizeof(float) * 2 * BB * KCC * DD);

    conv_w_kernel<<<dim3(1024, 2), 256>>>(E_w, F_w);
    proj_mma_kernel<<<dim3(4, BB / 2, 2), 256, proj_smem>>>(K, V);
    finalize_kernel<<<dim3(BB * 4, 2), 256>>>(E_b, F_b);
    attn_kernel<<<dim3(4, BB), 256, attn_smem>>>(Q, out);
}

// round 15
// speedup vs baseline: 1.0895x; 1.0895x over previous
#include <cuda_runtime.h>
#include <cuda_bf16.h>
#include <cuda_fp16.h>
#include <cstdint>

#define BB 32
#define SS 4096
#define DD 64
#define KCC 256

// ------------------------- device global scratch ---------------------------
__device__ __half g_Wh[2 * KCC * SS];        // [proj][kc][s] fp16
__device__ float  g_acc[2 * BB * KCC * DD];  // [proj][b][kc][d] fp32 partials
__device__ __half g_Ke16[BB * KCC * DD];     // [b][kc][d] fp16 (Ke^T + bias)
__device__ __half g_Vf16[BB * KCC * DD];     // [b][kc][d] fp16 (Vf + bias)

// ------------------------------ helpers ------------------------------------
__device__ __forceinline__ uint32_t smem_u32(const void* p) {
    uint32_t a;
    asm("{ .reg .u64 t; cvta.to.shared.u64 t, %1; cvt.u32.u64 %0, t; }"
        : "=r"(a) : "l"(p));
    return a;
}
#define SW128(x) ((x) ^ (((x) >> 3) & 0x70))

__device__ __forceinline__ void cp16(uint32_t dst, const void* src) {
    asm volatile("cp.async.cg.shared.global [%0], [%1], 16;"
                 :: "r"(dst), "l"(src) : "memory");
}
__device__ __forceinline__ void cp_commit() {
    asm volatile("cp.async.commit_group;" ::: "memory");
}
template <int N>
__device__ __forceinline__ void cp_wait() {
    asm volatile("cp.async.wait_group %0;" :: "n"(N) : "memory");
}
__device__ __forceinline__ void ldm_x4(uint32_t* r, uint32_t addr) {
    asm volatile("ldmatrix.sync.aligned.m8n8.x4.shared.b16 {%0,%1,%2,%3}, [%4];"
                 : "=r"(r[0]), "=r"(r[1]), "=r"(r[2]), "=r"(r[3]) : "r"(addr));
}
__device__ __forceinline__ void ldm_x4_t(uint32_t* r, uint32_t addr) {
    asm volatile("ldmatrix.sync.aligned.m8n8.x4.trans.shared.b16 {%0,%1,%2,%3}, [%4];"
                 : "=r"(r[0]), "=r"(r[1]), "=r"(r[2]), "=r"(r[3]) : "r"(addr));
}
__device__ __forceinline__ void mma_f16(
    float* c, const uint32_t* a, uint32_t b0, uint32_t b1) {
    asm volatile(
        "mma.sync.aligned.m16n8k16.row.col.f32.f16.f16.f32 "
        "{%0,%1,%2,%3}, {%4,%5,%6,%7}, {%8,%9}, {%0,%1,%2,%3};"
        : "+f"(c[0]), "+f"(c[1]), "+f"(c[2]), "+f"(c[3])
        : "r"(a[0]), "r"(a[1]), "r"(a[2]), "r"(a[3]), "r"(b0), "r"(b1));
}
__device__ __forceinline__ uint32_t packhf(float lo, float hi) {
    uint32_t r;
    asm("cvt.rn.f16x2.f32 %0, %1, %2;" : "=r"(r) : "f"(hi), "f"(lo));
    return r;
}
__device__ __forceinline__ float hfres(float v) {   // v - fp16(v)
    return v - __half2float(__float2half(v));
}

// ---------------------------------------------------------------------------
// conv_w: E_w / F_w (fp32 [256][4096]) -> fp16, same layout. Grid (1024, 2).
// ---------------------------------------------------------------------------
__global__ __launch_bounds__(256) void conv_w_kernel(
    const float* __restrict__ Ew, const float* __restrict__ Fw)
{
    const int y = blockIdx.y;
    const float4* src = reinterpret_cast<const float4*>(y ? Fw : Ew);
    const int i = blockIdx.x * 256 + threadIdx.x;
    float4 v = src[i];
    __half2* oh = reinterpret_cast<__half2*>(g_Wh + (size_t)y * KCC * SS) + 2 * i;
    oh[0] = __halves2half2(__float2half(v.x), __float2half(v.y));
    oh[1] = __halves2half2(__float2half(v.z), __float2half(v.w));
}

// ---------------------------------------------------------------------------
// proj_mma: mma.sync fp16 GEMM; s-quarter split + 2 batches per CTA.
// Grid (4, 16, 2) = 128 CTAs. Block 256. ONE sync per chunk: load of chunk
// c+2 issued AFTER the barrier (all warps past it have finished MMA(c-1),
// so overwriting W/Xf stage (c+2)%3 = (c-1)%3 is safe).
// SMEM: W 3x32KB @0 | Xf 3x32KB @98304 | Xh 2x16KB @196608 = 224 KB.
// ---------------------------------------------------------------------------
__global__ __launch_bounds__(256) void proj_mma_kernel(
    const float* __restrict__ Kf, const float* __restrict__ Vf)
{
    extern __shared__ char sm[];
    const uint32_t smb = smem_u32(sm);
    const int tid = threadIdx.x, wid = tid >> 5, lane = tid & 31;
    const int sq = blockIdx.x, bp = blockIdx.y, proj = blockIdx.z;
    const int mw = wid >> 2, nw = wid & 3;
    const int g = lane >> 2, q = lane & 3;

    const __half* Wh = g_Wh + (size_t)proj * KCC * SS;
    const float* Xsrc = proj ? Vf : Kf;
    const float* Xb[2] = { Xsrc + (size_t)(2 * bp) * SS * DD,
                           Xsrc + (size_t)(2 * bp + 1) * SS * DD };
    const int sbase = sq * 1024;

    float acc[2][8][2][4];
#pragma unroll
    for (int bb = 0; bb < 2; bb++)
#pragma unroll
        for (int mf = 0; mf < 8; mf++)
#pragma unroll
            for (int nf = 0; nf < 2; nf++)
#pragma unroll
                for (int i = 0; i < 4; i++) acc[bb][mf][nf][i] = 0.f;

    const int NC = 1024 / 64;   // 16 chunks

    auto load_chunk = [&](int c) {
        const uint32_t wbuf = smb + (c % 3) * 32768;
#pragma unroll
        for (int idx = tid; idx < 2048; idx += 256) {
            int row = idx >> 3, s16 = idx & 7;
            size_t so = (size_t)row * SS + sbase + c * 64 + s16 * 8;
            uint32_t bo = SW128((uint32_t)(row * 128 + s16 * 16));
            cp16(wbuf + bo, Wh + so);
        }
        const uint32_t xfbuf = smb + 98304 + (c % 3) * 32768;
#pragma unroll
        for (int bb = 0; bb < 2; bb++) {
            const float* xsrc = Xb[bb] + (size_t)(sbase + c * 64) * DD;
#pragma unroll
            for (int u = 0; u < 2; u++) {
                int seg = tid + u * 256;
                cp16(xfbuf + bb * 16384 + seg * 32,      xsrc + seg * 8);
                cp16(xfbuf + bb * 16384 + seg * 32 + 16, xsrc + seg * 8 + 4);
            }
        }
        cp_commit();
    };

    auto convert_x = [&](int c) {
        const char* xf = sm + 98304 + (c % 3) * 32768;
        char* xbb = sm + 196608 + (c & 1) * 16384;
#pragma unroll
        for (int bb = 0; bb < 2; bb++)
#pragma unroll
            for (int u = 0; u < 2; u++) {
                int seg = tid + u * 256;
                int row = seg >> 3, s16 = seg & 7;
                float4 v0 = *reinterpret_cast<const float4*>(
                    xf + bb * 16384 + seg * 32);
                float4 v1 = *reinterpret_cast<const float4*>(
                    xf + bb * 16384 + seg * 32 + 16);
                uint32_t bo = SW128((uint32_t)(row * 128 + s16 * 16));
                uint4 h;
                h.x = packhf(v0.x, v0.y); h.y = packhf(v0.z, v0.w);
                h.z = packhf(v1.x, v1.y); h.w = packhf(v1.z, v1.w);
                *reinterpret_cast<uint4*>(xbb + bb * 8192 + bo) = h;
            }
    };

    load_chunk(0); load_chunk(1);

    for (int c = 0; c < NC; c++) {
        cp_wait<1>();          // chunk c's group complete
        convert_x(c);
        __syncthreads();       // Xh(c) visible; all warps past MMA(c-1)
        if (c + 2 < NC) load_chunk(c + 2);

        const uint32_t Ah = smb + (c % 3) * 32768;
        const uint32_t Xh = smb + 196608 + (c & 1) * 16384;
        const int lr = lane & 15, lc = (lane >> 4) * 16;

#pragma unroll
        for (int kk = 0; kk < 4; kk++) {
            uint32_t bh[2][4];
            uint32_t boff = SW128((uint32_t)((kk * 16 + lr) * 128 + nw * 32 + lc));
            ldm_x4_t(bh[0], Xh + boff);
            ldm_x4_t(bh[1], Xh + 8192 + boff);
#pragma unroll
            for (int mf = 0; mf < 8; mf++) {
                uint32_t ah[4];
                uint32_t off = SW128((uint32_t)(
                    (mw * 128 + mf * 16 + lr) * 128 + kk * 32 + lc));
                ldm_x4(ah, Ah + off);
#pragma unroll
                for (int bb = 0; bb < 2; bb++)
#pragma unroll
                    for (int nf = 0; nf < 2; nf++)
                        mma_f16(acc[bb][mf][nf], ah,
                                bh[bb][2 * nf], bh[bb][2 * nf + 1]);
            }
        }
    }

    // ---- epilogue: vector float2 atomics into g_acc ----
#pragma unroll
    for (int bb = 0; bb < 2; bb++) {
        float* out = g_acc + ((size_t)proj * BB + 2 * bp + bb) * KCC * DD;
#pragma unroll
        for (int mf = 0; mf < 8; mf++) {
            const int kcl = mw * 128 + mf * 16 + g;
#pragma unroll
            for (int nf = 0; nf < 2; nf++) {
                const int d0 = nw * 16 + nf * 8 + 2 * q;
                atomicAdd(reinterpret_cast<float2*>(&out[(size_t)kcl * DD + d0]),
                          make_float2(acc[bb][mf][nf][0], acc[bb][mf][nf][1]));
                atomicAdd(reinterpret_cast<float2*>(&out[(size_t)(kcl + 8) * DD + d0]),
                          make_float2(acc[bb][mf][nf][2], acc[bb][mf][nf][3]));
            }
        }
    }
}

// ---------------------------------------------------------------------------
// finalize: g_acc (+bias) -> single fp16 arrays. Grid (BB*4, 2). Block 256.
// ---------------------------------------------------------------------------
__global__ __launch_bounds__(256) void finalize_kernel(
    const float* __restrict__ E_b, const float* __restrict__ F_b)
{
    const int blk = blockIdx.x, proj = blockIdx.y;
    const int b = blk >> 2, quarter = blk & 3;
    const float* src = g_acc + ((size_t)proj * BB + b) * KCC * DD;
    const float* bias = proj ? F_b : E_b;
    __half* oh = (proj ? g_Vf16 : g_Ke16) + (size_t)b * KCC * DD;

    const int i0 = quarter * 1024;
#pragma unroll
    for (int t = 0; t < 4; t++) {
        const int i = i0 + t * 256 + threadIdx.x;
        const int kc = (i * 4) >> 6;
        const float bv = bias[kc];
        float4 v = reinterpret_cast<const float4*>(src)[i];
        uint2 h;
        h.x = packhf(v.x + bv, v.y + bv);
        h.y = packhf(v.z + bv, v.w + bv);
        reinterpret_cast<uint2*>(oh)[i] = h;
    }
}

// ---------------------------------------------------------------------------
// attn: fp16 tensor-core attention (rows 0..255) + fused broadcast.
//   GEMM1 = Qh*Ke + Ql*Ke (Q exact in fp16 hi/lo; Ke single fp16)
//   GEMM2 = Ph*Vf + Pl*Vf (P exact; Vf single fp16)
// Grid (4, B). Block 256: warps 0-3 MMA, all warps load/broadcast.
// SMEM: Ke 32K | Vf 32K | Qh 8K | Ql 8K = 80KB.
// ---------------------------------------------------------------------------
__global__ __launch_bounds__(256) void attn_kernel(
    const float* __restrict__ Qf, float* __restrict__ out)
{
    extern __shared__ char sm[];
    const uint32_t smb = smem_u32(sm);
    const uint32_t KE = 0, VF = 32768, QH = 65536, QL = 73728;

    const int tid = threadIdx.x, lane = tid & 31, warp = tid >> 5;
    const int b = blockIdx.y;
    const int s0 = blockIdx.x * 64;
    const int g = lane >> 2, q = lane & 3;
    const int lr = lane & 15, lcb = (lane >> 4) * 16;

    // ---- Ke / Vf fp16 tiles via cp.async ----
    {
        const __half* ke = g_Ke16 + (size_t)b * KCC * DD;
        const __half* vf = g_Vf16 + (size_t)b * KCC * DD;
#pragma unroll
        for (int idx = tid; idx < 2048; idx += 256) {
            int row = idx >> 3, seg = idx & 7;
            size_t so = (size_t)row * DD + seg * 8;
            uint32_t bo = SW128((uint32_t)(row * 128 + seg * 16));
            cp16(smb + KE + bo, ke + so);
            cp16(smb + VF + bo, vf + so);
        }
        cp_commit();
    }
    // ---- Q: fp32 -> fp16 hi/lo smem ----
    {
        const float* qb = Qf + ((size_t)b * SS + s0) * DD;
#pragma unroll
        for (int idx = tid; idx < 512; idx += 256) {
            int row = idx >> 3, seg = idx & 7;
            const float* qp = qb + (size_t)row * DD + seg * 8;
            float4 v0 = *reinterpret_cast<const float4*>(qp);
            float4 v1 = *reinterpret_cast<const float4*>(qp + 4);
            uint32_t bo = SW128((uint32_t)(row * 128 + seg * 16));
            uint4 h, l;
            h.x = packhf(v0.x, v0.y); h.y = packhf(v0.z, v0.w);
            h.z = packhf(v1.x, v1.y); h.w = packhf(v1.z, v1.w);
            l.x = packhf(hfres(v0.x), hfres(v0.y));
            l.y = packhf(hfres(v0.z), hfres(v0.w));
            l.z = packhf(hfres(v1.x), hfres(v1.y));
            l.w = packhf(hfres(v1.z), hfres(v1.w));
            *reinterpret_cast<uint4*>(sm + QH + bo) = h;
            *reinterpret_cast<uint4*>(sm + QL + bo) = l;
        }
        cp_wait<0>();
        __syncthreads();
    }

    if (warp < 4) {
        const int j0 = blockIdx.x * 4 + warp;   // first unmasked kc tile

        float acc[32][4];
#pragma unroll
        for (int nf = 0; nf < 32; nf++)
#pragma unroll
            for (int i = 0; i < 4; i++) acc[nf][i] = 0.f;

#pragma unroll
        for (int kk = 0; kk < 4; kk++) {
            uint32_t qh[4], ql[4];
            uint32_t offA = SW128((uint32_t)((warp * 16 + lr) * 128 + kk * 32 + lcb));
            ldm_x4(qh, smb + QH + offA);
            ldm_x4(ql, smb + QL + offA);
#pragma unroll
            for (int j = 0; j < 16; j++) {
                if (j >= j0) {
                    uint32_t off = SW128((uint32_t)((j * 16 + lr) * 128 + kk * 32 + lcb));
                    uint32_t bh[4];
                    ldm_x4(bh, smb + KE + off);
                    mma_f16(acc[2 * j],     qh, bh[0], bh[2]);
                    mma_f16(acc[2 * j],     ql, bh[0], bh[2]);
                    mma_f16(acc[2 * j + 1], qh, bh[1], bh[3]);
                    mma_f16(acc[2 * j + 1], ql, bh[1], bh[3]);
                }
            }
        }

        const int rowa = s0 + warp * 16 + g;
        const int rowb = rowa + 8;
        float mxa = -3.4e38f, mxb = -3.4e38f;
#pragma unroll
        for (int nf = 0; nf < 32; nf++) {
            const int kc = 8 * nf + 2 * q;
            acc[nf][0] = (kc     >= rowa) ? acc[nf][0] * 0.125f : -1e10f;
            acc[nf][1] = (kc + 1 >= rowa) ? acc[nf][1] * 0.125f : -1e10f;
            acc[nf][2] = (kc     >= rowb) ? acc[nf][2] * 0.125f : -1e10f;
            acc[nf][3] = (kc + 1 >= rowb) ? acc[nf][3] * 0.125f : -1e10f;
            mxa = fmaxf(mxa, fmaxf(acc[nf][0], acc[nf][1]));
            mxb = fmaxf(mxb, fmaxf(acc[nf][2], acc[nf][3]));
        }
#pragma unroll
        for (int o = 1; o <= 2; o <<= 1) {
            mxa = fmaxf(mxa, __shfl_xor_sync(0xffffffffu, mxa, o));
            mxb = fmaxf(mxb, __shfl_xor_sync(0xffffffffu, mxb, o));
        }
        float sa = 0.f, sb = 0.f;
#pragma unroll
        for (int nf = 0; nf < 32; nf++) {
            acc[nf][0] = __expf(acc[nf][0] - mxa);
            acc[nf][1] = __expf(acc[nf][1] - mxa);
            acc[nf][2] = __expf(acc[nf][2] - mxb);
            acc[nf][3] = __expf(acc[nf][3] - mxb);
            sa += acc[nf][0] + acc[nf][1];
            sb += acc[nf][2] + acc[nf][3];
        }
#pragma unroll
        for (int o = 1; o <= 2; o <<= 1) {
            sa += __shfl_xor_sync(0xffffffffu, sa, o);
            sb += __shfl_xor_sync(0xffffffffu, sb, o);
        }
        const float inva = 1.f / sa, invb = 1.f / sb;

        uint32_t pAh[32], pAl[32], pBh[32], pBl[32];
#pragma unroll
        for (int nf = 0; nf < 32; nf++) {
            float p0 = acc[nf][0] * inva, p1 = acc[nf][1] * inva;
            float p2 = acc[nf][2] * invb, p3 = acc[nf][3] * invb;
            pAh[nf] = packhf(p0, p1);
            pBh[nf] = packhf(p2, p3);
            pAl[nf] = packhf(hfres(p0), hfres(p1));
            pBl[nf] = packhf(hfres(p2), hfres(p3));
        }

        float acc2[8][4];
#pragma unroll
        for (int u = 0; u < 8; u++)
#pragma unroll
            for (int i = 0; i < 4; i++) acc2[u][i] = 0.f;

#pragma unroll
        for (int ks = 0; ks < 16; ks++) {
            if (ks >= j0) {
                uint32_t a_h[4] = {pAh[2 * ks], pBh[2 * ks],
                                   pAh[2 * ks + 1], pBh[2 * ks + 1]};
                uint32_t a_l[4] = {pAl[2 * ks], pBl[2 * ks],
                                   pAl[2 * ks + 1], pBl[2 * ks + 1]};
#pragma unroll
                for (int t = 0; t < 4; t++) {
                    uint32_t off = SW128((uint32_t)((ks * 16 + lr) * 128 + t * 32 + lcb));
                    uint32_t vh[4];
                    ldm_x4_t(vh, smb + VF + off);
                    mma_f16(acc2[2 * t],     a_h, vh[0], vh[1]);
                    mma_f16(acc2[2 * t],     a_l, vh[0], vh[1]);
                    mma_f16(acc2[2 * t + 1], a_h, vh[2], vh[3]);
                    mma_f16(acc2[2 * t + 1], a_l, vh[2], vh[3]);
                }
            }
        }

        float* ob = out + (size_t)b * SS * DD;
#pragma unroll
        for (int u = 0; u < 8; u++) {
            const int d0 = 8 * u + 2 * q;
            *reinterpret_cast<float2*>(&ob[(size_t)rowa * DD + d0]) =
                make_float2(acc2[u][0], acc2[u][1]);
            *reinterpret_cast<float2*>(&ob[(size_t)rowb * DD + d0]) =
                make_float2(acc2[u][2], acc2[u][3]);
        }
    }

    // ---- fused broadcast (8 warps): rows >= KC get mean_k Vf[k][:]. ----
    __syncthreads();
    {
        float* red = reinterpret_cast<float*>(sm + QH);          // [8][64]
        float* meanv = reinterpret_cast<float*>(sm + QH) + 512;  // [64]
        const int dp = tid & 31, kq = tid >> 5;
        float m0 = 0.f, m1 = 0.f;
        for (int k = kq * 32; k < kq * 32 + 32; k++) {
            uint32_t off = SW128((uint32_t)(k * 128 + dp * 4));
            uint32_t hw = *reinterpret_cast<const uint32_t*>(sm + VF + off);
            __half2 hv = *reinterpret_cast<__half2*>(&hw);
            m0 += __half2float(hv.x);
            m1 += __half2float(hv.y);
        }
        red[kq * 64 + 2 * dp]     = m0;
        red[kq * 64 + 2 * dp + 1] = m1;
        __syncthreads();
        if (tid < 64) {
            float t = 0.f;
#pragma unroll
            for (int k = 0; k < 8; k++) t += red[k * 64 + tid];
            meanv[tid] = t * (1.f / 256.f);
        }
        __syncthreads();

        const int ccol = tid & 15, rofs = tid >> 4;
        const float4 val = make_float4(meanv[ccol * 4], meanv[ccol * 4 + 1],
                                       meanv[ccol * 4 + 2], meanv[ccol * 4 + 3]);
        float4* obv = reinterpret_cast<float4*>(out + (size_t)b * SS * DD);
        const int r0b = KCC + blockIdx.x * 960;
#pragma unroll 4
        for (int r = r0b + rofs; r < r0b + 960; r += 16)
            obv[(size_t)r * 16 + ccol] = val;
    }
}

// ---------------------------------------------------------------------------
// Harness entry. Inputs: Q, K, V, E_w, E_b, F_w, F_b. Output f32 [B,S,D].
// ---------------------------------------------------------------------------
extern "C" void kernel_launch(void* const* d_in, const int* in_sizes, int n_in,
                              void* d_out, int out_size)
{
    (void)in_sizes; (void)n_in; (void)out_size;
    const float* Q   = (const float*)d_in[0];
    const float* K   = (const float*)d_in[1];
    const float* V   = (const float*)d_in[2];
    const float* E_w = (const float*)d_in[3];
    const float* E_b = (const float*)d_in[4];
    const float* F_w = (const float*)d_in[5];
    const float* F_b = (const float*)d_in[6];
    float* out = (float*)d_out;

    const int proj_smem = 229376;   // 224 KB
    const int attn_smem = 81920;    // 80 KB
    cudaFuncSetAttribute(proj_mma_kernel,
                         cudaFuncAttributeMaxDynamicSharedMemorySize, proj_smem);
    cudaFuncSetAttribute(attn_kernel,
                         cudaFuncAttributeMaxDynamicSharedMemorySize, attn_smem);

    void* accptr = nullptr;
    cudaGetSymbolAddress(&accptr, g_acc);
    cudaMemsetAsync(accptr, 0, sizeof(float) * 2 * BB * KCC * DD);

    conv_w_kernel<<<dim3(1024, 2), 256>>>(E_w, F_w);
    proj_mma_kernel<<<dim3(4, BB / 2, 2), 256, proj_smem>>>(K, V);
    finalize_kernel<<<dim3(BB * 4, 2), 256>>>(E_b, F_b);
    attn_kernel<<<dim3(4, BB), 256, attn_smem>>>(Q, out);
}

// round 16
// speedup vs baseline: 1.0960x; 1.0060x over previous
#include <cuda_runtime.h>
#include <cuda_bf16.h>
#include <cuda_fp16.h>
#include <cstdint>

#define BB 32
#define SS 4096
#define DD 64
#define KCC 256

// ------------------------- device global scratch ---------------------------
__device__ __half g_Wh[2 * KCC * SS];        // [proj][kc][s] fp16
__device__ float  g_acc[2 * BB * KCC * DD];  // [proj][b][kc][d] fp32 partials
__device__ __half g_Ke16[BB * KCC * DD];     // [b][kc][d] fp16 (Ke^T + bias)
__device__ __half g_Vf16[BB * KCC * DD];     // [b][kc][d] fp16 (Vf + bias)

// ------------------------------ helpers ------------------------------------
__device__ __forceinline__ uint32_t smem_u32(const void* p) {
    uint32_t a;
    asm("{ .reg .u64 t; cvta.to.shared.u64 t, %1; cvt.u32.u64 %0, t; }"
        : "=r"(a) : "l"(p));
    return a;
}
#define SW128(x) ((x) ^ (((x) >> 3) & 0x70))

__device__ __forceinline__ void cp16(uint32_t dst, const void* src) {
    asm volatile("cp.async.cg.shared.global [%0], [%1], 16;"
                 :: "r"(dst), "l"(src) : "memory");
}
__device__ __forceinline__ void cp_commit() {
    asm volatile("cp.async.commit_group;" ::: "memory");
}
template <int N>
__device__ __forceinline__ void cp_wait() {
    asm volatile("cp.async.wait_group %0;" :: "n"(N) : "memory");
}
__device__ __forceinline__ void ldm_x4(uint32_t* r, uint32_t addr) {
    asm volatile("ldmatrix.sync.aligned.m8n8.x4.shared.b16 {%0,%1,%2,%3}, [%4];"
                 : "=r"(r[0]), "=r"(r[1]), "=r"(r[2]), "=r"(r[3]) : "r"(addr));
}
__device__ __forceinline__ void ldm_x4_t(uint32_t* r, uint32_t addr) {
    asm volatile("ldmatrix.sync.aligned.m8n8.x4.trans.shared.b16 {%0,%1,%2,%3}, [%4];"
                 : "=r"(r[0]), "=r"(r[1]), "=r"(r[2]), "=r"(r[3]) : "r"(addr));
}
__device__ __forceinline__ void mma_f16(
    float* c, const uint32_t* a, uint32_t b0, uint32_t b1) {
    asm volatile(
        "mma.sync.aligned.m16n8k16.row.col.f32.f16.f16.f32 "
        "{%0,%1,%2,%3}, {%4,%5,%6,%7}, {%8,%9}, {%0,%1,%2,%3};"
        : "+f"(c[0]), "+f"(c[1]), "+f"(c[2]), "+f"(c[3])
        : "r"(a[0]), "r"(a[1]), "r"(a[2]), "r"(a[3]), "r"(b0), "r"(b1));
}
__device__ __forceinline__ uint32_t packhf(float lo, float hi) {
    uint32_t r;
    asm("cvt.rn.f16x2.f32 %0, %1, %2;" : "=r"(r) : "f"(hi), "f"(lo));
    return r;
}
__device__ __forceinline__ float hfres(float v) {   // v - fp16(v)
    return v - __half2float(__float2half(v));
}

// ---------------------------------------------------------------------------
// conv_w: E_w / F_w (fp32 [256][4096]) -> fp16, same layout. Grid (1024, 2).
// ---------------------------------------------------------------------------
__global__ __launch_bounds__(256) void conv_w_kernel(
    const float* __restrict__ Ew, const float* __restrict__ Fw)
{
    const int y = blockIdx.y;
    const float4* src = reinterpret_cast<const float4*>(y ? Fw : Ew);
    const int i = blockIdx.x * 256 + threadIdx.x;
    float4 v = src[i];
    __half2* oh = reinterpret_cast<__half2*>(g_Wh + (size_t)y * KCC * SS) + 2 * i;
    oh[0] = __halves2half2(__float2half(v.x), __float2half(v.y));
    oh[1] = __halves2half2(__float2half(v.z), __float2half(v.w));
}

// ---------------------------------------------------------------------------
// proj_mma: mma.sync fp16 GEMM; s-quarter split + 2 batches per CTA.
// Grid (4, 16, 2) = 128 CTAs. Block 256. One sync per chunk.
// SMEM: W 3x32KB @0 | Xf 3x32KB @98304 | Xh 2x16KB @196608 = 224 KB.
// ---------------------------------------------------------------------------
__global__ __launch_bounds__(256) void proj_mma_kernel(
    const float* __restrict__ Kf, const float* __restrict__ Vf)
{
    extern __shared__ char sm[];
    const uint32_t smb = smem_u32(sm);
    const int tid = threadIdx.x, wid = tid >> 5, lane = tid & 31;
    const int sq = blockIdx.x, bp = blockIdx.y, proj = blockIdx.z;
    const int mw = wid >> 2, nw = wid & 3;
    const int g = lane >> 2, q = lane & 3;

    const __half* Wh = g_Wh + (size_t)proj * KCC * SS;
    const float* Xsrc = proj ? Vf : Kf;
    const float* Xb[2] = { Xsrc + (size_t)(2 * bp) * SS * DD,
                           Xsrc + (size_t)(2 * bp + 1) * SS * DD };
    const int sbase = sq * 1024;

    float acc[2][8][2][4];
#pragma unroll
    for (int bb = 0; bb < 2; bb++)
#pragma unroll
        for (int mf = 0; mf < 8; mf++)
#pragma unroll
            for (int nf = 0; nf < 2; nf++)
#pragma unroll
                for (int i = 0; i < 4; i++) acc[bb][mf][nf][i] = 0.f;

    const int NC = 1024 / 64;   // 16 chunks

    auto load_chunk = [&](int c) {
        const uint32_t wbuf = smb + (c % 3) * 32768;
#pragma unroll
        for (int idx = tid; idx < 2048; idx += 256) {
            int row = idx >> 3, s16 = idx & 7;
            size_t so = (size_t)row * SS + sbase + c * 64 + s16 * 8;
            uint32_t bo = SW128((uint32_t)(row * 128 + s16 * 16));
            cp16(wbuf + bo, Wh + so);
        }
        const uint32_t xfbuf = smb + 98304 + (c % 3) * 32768;
#pragma unroll
        for (int bb = 0; bb < 2; bb++) {
            const float* xsrc = Xb[bb] + (size_t)(sbase + c * 64) * DD;
#pragma unroll
            for (int u = 0; u < 2; u++) {
                int seg = tid + u * 256;
                cp16(xfbuf + bb * 16384 + seg * 32,      xsrc + seg * 8);
                cp16(xfbuf + bb * 16384 + seg * 32 + 16, xsrc + seg * 8 + 4);
            }
        }
        cp_commit();
    };

    auto convert_x = [&](int c) {
        const char* xf = sm + 98304 + (c % 3) * 32768;
        char* xbb = sm + 196608 + (c & 1) * 16384;
#pragma unroll
        for (int bb = 0; bb < 2; bb++)
#pragma unroll
            for (int u = 0; u < 2; u++) {
                int seg = tid + u * 256;
                int row = seg >> 3, s16 = seg & 7;
                float4 v0 = *reinterpret_cast<const float4*>(
                    xf + bb * 16384 + seg * 32);
                float4 v1 = *reinterpret_cast<const float4*>(
                    xf + bb * 16384 + seg * 32 + 16);
                uint32_t bo = SW128((uint32_t)(row * 128 + s16 * 16));
                uint4 h;
                h.x = packhf(v0.x, v0.y); h.y = packhf(v0.z, v0.w);
                h.z = packhf(v1.x, v1.y); h.w = packhf(v1.z, v1.w);
                *reinterpret_cast<uint4*>(xbb + bb * 8192 + bo) = h;
            }
    };

    load_chunk(0); load_chunk(1);

    for (int c = 0; c < NC; c++) {
        cp_wait<1>();
        convert_x(c);
        __syncthreads();
        if (c + 2 < NC) load_chunk(c + 2);

        const uint32_t Ah = smb + (c % 3) * 32768;
        const uint32_t Xh = smb + 196608 + (c & 1) * 16384;
        const int lr = lane & 15, lc = (lane >> 4) * 16;

#pragma unroll
        for (int kk = 0; kk < 4; kk++) {
            uint32_t bh[2][4];
            uint32_t boff = SW128((uint32_t)((kk * 16 + lr) * 128 + nw * 32 + lc));
            ldm_x4_t(bh[0], Xh + boff);
            ldm_x4_t(bh[1], Xh + 8192 + boff);
#pragma unroll
            for (int mf = 0; mf < 8; mf++) {
                uint32_t ah[4];
                uint32_t off = SW128((uint32_t)(
                    (mw * 128 + mf * 16 + lr) * 128 + kk * 32 + lc));
                ldm_x4(ah, Ah + off);
#pragma unroll
                for (int bb = 0; bb < 2; bb++)
#pragma unroll
                    for (int nf = 0; nf < 2; nf++)
                        mma_f16(acc[bb][mf][nf], ah,
                                bh[bb][2 * nf], bh[bb][2 * nf + 1]);
            }
        }
    }

    // ---- epilogue: vector float2 atomics into g_acc ----
#pragma unroll
    for (int bb = 0; bb < 2; bb++) {
        float* out = g_acc + ((size_t)proj * BB + 2 * bp + bb) * KCC * DD;
#pragma unroll
        for (int mf = 0; mf < 8; mf++) {
            const int kcl = mw * 128 + mf * 16 + g;
#pragma unroll
            for (int nf = 0; nf < 2; nf++) {
                const int d0 = nw * 16 + nf * 8 + 2 * q;
                atomicAdd(reinterpret_cast<float2*>(&out[(size_t)kcl * DD + d0]),
                          make_float2(acc[bb][mf][nf][0], acc[bb][mf][nf][1]));
                atomicAdd(reinterpret_cast<float2*>(&out[(size_t)(kcl + 8) * DD + d0]),
                          make_float2(acc[bb][mf][nf][2], acc[bb][mf][nf][3]));
            }
        }
    }
}

// ---------------------------------------------------------------------------
// finalize: g_acc (+bias) -> single fp16 arrays. Grid (BB*4, 2). Block 256.
// ---------------------------------------------------------------------------
__global__ __launch_bounds__(256) void finalize_kernel(
    const float* __restrict__ E_b, const float* __restrict__ F_b)
{
    const int blk = blockIdx.x, proj = blockIdx.y;
    const int b = blk >> 2, quarter = blk & 3;
    const float* src = g_acc + ((size_t)proj * BB + b) * KCC * DD;
    const float* bias = proj ? F_b : E_b;
    __half* oh = (proj ? g_Vf16 : g_Ke16) + (size_t)b * KCC * DD;

    const int i0 = quarter * 1024;
#pragma unroll
    for (int t = 0; t < 4; t++) {
        const int i = i0 + t * 256 + threadIdx.x;
        const int kc = (i * 4) >> 6;
        const float bv = bias[kc];
        float4 v = reinterpret_cast<const float4*>(src)[i];
        uint2 h;
        h.x = packhf(v.x + bv, v.y + bv);
        h.y = packhf(v.z + bv, v.w + bv);
        reinterpret_cast<uint2*>(oh)[i] = h;
    }
}

// ---------------------------------------------------------------------------
// attn: fp16 tensor-core attention (rows 0..255) + fused broadcast.
// Grid (8, B) = 256 blocks. Block 128 (4 warps): warps 0-1 do MMA (16 rows
// each, 32 rows/block); all warps load and broadcast (480 rows/block).
// 2 CTAs/SM -> real latency overlap.
// SMEM: Ke 32K | Vf 32K | Qh 4K | Ql 4K = 72KB.
// ---------------------------------------------------------------------------
__global__ __launch_bounds__(128) void attn_kernel(
    const float* __restrict__ Qf, float* __restrict__ out)
{
    extern __shared__ char sm[];
    const uint32_t smb = smem_u32(sm);
    const uint32_t KE = 0, VF = 32768, QH = 65536, QL = 69632;

    const int tid = threadIdx.x, lane = tid & 31, warp = tid >> 5;
    const int b = blockIdx.y;
    const int s0 = blockIdx.x * 32;
    const int g = lane >> 2, q = lane & 3;
    const int lr = lane & 15, lcb = (lane >> 4) * 16;

    // ---- Ke / Vf fp16 tiles via cp.async (128 threads) ----
    {
        const __half* ke = g_Ke16 + (size_t)b * KCC * DD;
        const __half* vf = g_Vf16 + (size_t)b * KCC * DD;
#pragma unroll
        for (int idx = tid; idx < 2048; idx += 128) {
            int row = idx >> 3, seg = idx & 7;
            size_t so = (size_t)row * DD + seg * 8;
            uint32_t bo = SW128((uint32_t)(row * 128 + seg * 16));
            cp16(smb + KE + bo, ke + so);
            cp16(smb + VF + bo, vf + so);
        }
        cp_commit();
    }
    // ---- Q: fp32 -> fp16 hi/lo smem (32 rows) ----
    {
        const float* qb = Qf + ((size_t)b * SS + s0) * DD;
#pragma unroll
        for (int idx = tid; idx < 256; idx += 128) {
            int row = idx >> 3, seg = idx & 7;
            const float* qp = qb + (size_t)row * DD + seg * 8;
            float4 v0 = *reinterpret_cast<const float4*>(qp);
            float4 v1 = *reinterpret_cast<const float4*>(qp + 4);
            uint32_t bo = SW128((uint32_t)(row * 128 + seg * 16));
            uint4 h, l;
            h.x = packhf(v0.x, v0.y); h.y = packhf(v0.z, v0.w);
            h.z = packhf(v1.x, v1.y); h.w = packhf(v1.z, v1.w);
            l.x = packhf(hfres(v0.x), hfres(v0.y));
            l.y = packhf(hfres(v0.z), hfres(v0.w));
            l.z = packhf(hfres(v1.x), hfres(v1.y));
            l.w = packhf(hfres(v1.z), hfres(v1.w));
            *reinterpret_cast<uint4*>(sm + QH + bo) = h;
            *reinterpret_cast<uint4*>(sm + QL + bo) = l;
        }
        cp_wait<0>();
        __syncthreads();
    }

    if (warp < 2) {
        const int j0 = blockIdx.x * 2 + warp;   // first unmasked kc tile

        float acc[32][4];
#pragma unroll
        for (int nf = 0; nf < 32; nf++)
#pragma unroll
            for (int i = 0; i < 4; i++) acc[nf][i] = 0.f;

#pragma unroll
        for (int kk = 0; kk < 4; kk++) {
            uint32_t qh[4], ql[4];
            uint32_t offA = SW128((uint32_t)((warp * 16 + lr) * 128 + kk * 32 + lcb));
            ldm_x4(qh, smb + QH + offA);
            ldm_x4(ql, smb + QL + offA);
#pragma unroll
            for (int j = 0; j < 16; j++) {
                if (j >= j0) {
                    uint32_t off = SW128((uint32_t)((j * 16 + lr) * 128 + kk * 32 + lcb));
                    uint32_t bh[4];
                    ldm_x4(bh, smb + KE + off);
                    mma_f16(acc[2 * j],     qh, bh[0], bh[2]);
                    mma_f16(acc[2 * j],     ql, bh[0], bh[2]);
                    mma_f16(acc[2 * j + 1], qh, bh[1], bh[3]);
                    mma_f16(acc[2 * j + 1], ql, bh[1], bh[3]);
                }
            }
        }

        const int rowa = s0 + warp * 16 + g;
        const int rowb = rowa + 8;
        float mxa = -3.4e38f, mxb = -3.4e38f;
#pragma unroll
        for (int nf = 0; nf < 32; nf++) {
            const int kc = 8 * nf + 2 * q;
            acc[nf][0] = (kc     >= rowa) ? acc[nf][0] * 0.125f : -1e10f;
            acc[nf][1] = (kc + 1 >= rowa) ? acc[nf][1] * 0.125f : -1e10f;
            acc[nf][2] = (kc     >= rowb) ? acc[nf][2] * 0.125f : -1e10f;
            acc[nf][3] = (kc + 1 >= rowb) ? acc[nf][3] * 0.125f : -1e10f;
            mxa = fmaxf(mxa, fmaxf(acc[nf][0], acc[nf][1]));
            mxb = fmaxf(mxb, fmaxf(acc[nf][2], acc[nf][3]));
        }
#pragma unroll
        for (int o = 1; o <= 2; o <<= 1) {
            mxa = fmaxf(mxa, __shfl_xor_sync(0xffffffffu, mxa, o));
            mxb = fmaxf(mxb, __shfl_xor_sync(0xffffffffu, mxb, o));
        }
        float sa = 0.f, sb = 0.f;
#pragma unroll
        for (int nf = 0; nf < 32; nf++) {
            acc[nf][0] = __expf(acc[nf][0] - mxa);
            acc[nf][1] = __expf(acc[nf][1] - mxa);
            acc[nf][2] = __expf(acc[nf][2] - mxb);
            acc[nf][3] = __expf(acc[nf][3] - mxb);
            sa += acc[nf][0] + acc[nf][1];
            sb += acc[nf][2] + acc[nf][3];
        }
#pragma unroll
        for (int o = 1; o <= 2; o <<= 1) {
            sa += __shfl_xor_sync(0xffffffffu, sa, o);
            sb += __shfl_xor_sync(0xffffffffu, sb, o);
        }
        const float inva = 1.f / sa, invb = 1.f / sb;

        uint32_t pAh[32], pAl[32], pBh[32], pBl[32];
#pragma unroll
        for (int nf = 0; nf < 32; nf++) {
            float p0 = acc[nf][0] * inva, p1 = acc[nf][1] * inva;
            float p2 = acc[nf][2] * invb, p3 = acc[nf][3] * invb;
            pAh[nf] = packhf(p0, p1);
            pBh[nf] = packhf(p2, p3);
            pAl[nf] = packhf(hfres(p0), hfres(p1));
            pBl[nf] = packhf(hfres(p2), hfres(p3));
        }

        float acc2[8][4];
#pragma unroll
        for (int u = 0; u < 8; u++)
#pragma unroll
            for (int i = 0; i < 4; i++) acc2[u][i] = 0.f;

#pragma unroll
        for (int ks = 0; ks < 16; ks++) {
            if (ks >= j0) {
                uint32_t a_h[4] = {pAh[2 * ks], pBh[2 * ks],
                                   pAh[2 * ks + 1], pBh[2 * ks + 1]};
                uint32_t a_l[4] = {pAl[2 * ks], pBl[2 * ks],
                                   pAl[2 * ks + 1], pBl[2 * ks + 1]};
#pragma unroll
                for (int t = 0; t < 4; t++) {
                    uint32_t off = SW128((uint32_t)((ks * 16 + lr) * 128 + t * 32 + lcb));
                    uint32_t vh[4];
                    ldm_x4_t(vh, smb + VF + off);
                    mma_f16(acc2[2 * t],     a_h, vh[0], vh[1]);
                    mma_f16(acc2[2 * t],     a_l, vh[0], vh[1]);
                    mma_f16(acc2[2 * t + 1], a_h, vh[2], vh[3]);
                    mma_f16(acc2[2 * t + 1], a_l, vh[2], vh[3]);
                }
            }
        }

        float* ob = out + (size_t)b * SS * DD;
#pragma unroll
        for (int u = 0; u < 8; u++) {
            const int d0 = 8 * u + 2 * q;
            *reinterpret_cast<float2*>(&ob[(size_t)rowa * DD + d0]) =
                make_float2(acc2[u][0], acc2[u][1]);
            *reinterpret_cast<float2*>(&ob[(size_t)rowb * DD + d0]) =
                make_float2(acc2[u][2], acc2[u][3]);
        }
    }

    // ---- fused broadcast (4 warps): rows >= KC get mean_k Vf[k][:]. ----
    __syncthreads();
    {
        float* red = reinterpret_cast<float*>(sm + QH);          // [4][64]
        float* meanv = reinterpret_cast<float*>(sm + QH) + 256;  // [64]
        const int dp = tid & 31, kq = tid >> 5;                  // 4 k-groups
        float m0 = 0.f, m1 = 0.f;
        for (int k = kq * 64; k < kq * 64 + 64; k++) {
            uint32_t off = SW128((uint32_t)(k * 128 + dp * 4));
            uint32_t hw = *reinterpret_cast<const uint32_t*>(sm + VF + off);
            __half2 hv = *reinterpret_cast<__half2*>(&hw);
            m0 += __half2float(hv.x);
            m1 += __half2float(hv.y);
        }
        red[kq * 64 + 2 * dp]     = m0;
        red[kq * 64 + 2 * dp + 1] = m1;
        __syncthreads();
        if (tid < 64)
            meanv[tid] = (red[tid] + red[64 + tid] + red[128 + tid] +
                          red[192 + tid]) * (1.f / 256.f);
        __syncthreads();

        const int ccol = tid & 15, rofs = tid >> 4;              // 8 row-lanes
        const float4 val = make_float4(meanv[ccol * 4], meanv[ccol * 4 + 1],
                                       meanv[ccol * 4 + 2], meanv[ccol * 4 + 3]);
        float4* obv = reinterpret_cast<float4*>(out + (size_t)b * SS * DD);
        const int r0b = KCC + blockIdx.x * 480;
#pragma unroll 4
        for (int r = r0b + rofs; r < r0b + 480; r += 8)
            obv[(size_t)r * 16 + ccol] = val;
    }
}

// ---------------------------------------------------------------------------
// Harness entry. Inputs: Q, K, V, E_w, E_b, F_w, F_b. Output f32 [B,S,D].
// ---------------------------------------------------------------------------
extern "C" void kernel_launch(void* const* d_in, const int* in_sizes, int n_in,
                              void* d_out, int out_size)
{
    (void)in_sizes; (void)n_in; (void)out_size;
    const float* Q   = (const float*)d_in[0];
    const float* K   = (const float*)d_in[1];
    const float* V   = (const float*)d_in[2];
    const float* E_w = (const float*)d_in[3];
    const float* E_b = (const float*)d_in[4];
    const float* F_w = (const float*)d_in[5];
    const float* F_b = (const float*)d_in[6];
    float* out = (float*)d_out;

    const int proj_smem = 229376;   // 224 KB
    const int attn_smem = 73728;    // 72 KB
    cudaFuncSetAttribute(proj_mma_kernel,
                         cudaFuncAttributeMaxDynamicSharedMemorySize, proj_smem);
    cudaFuncSetAttribute(attn_kernel,
                         cudaFuncAttributeMaxDynamicSharedMemorySize, attn_smem);

    void* accptr = nullptr;
    cudaGetSymbolAddress(&accptr, g_acc);
    cudaMemsetAsync(accptr, 0, sizeof(float) * 2 * BB * KCC * DD);

    conv_w_kernel<<<dim3(1024, 2), 256>>>(E_w, F_w);
    proj_mma_kernel<<<dim3(4, BB / 2, 2), 256, proj_smem>>>(K, V);
    finalize_kernel<<<dim3(BB * 4, 2), 256>>>(E_b, F_b);
    attn_kernel<<<dim3(8, BB), 128, attn_smem>>>(Q, out);
}

// round 17
// speedup vs baseline: 1.1654x; 1.0633x over previous
#include <cuda_runtime.h>
#include <cuda_bf16.h>
#include <cuda_fp16.h>
#include <cstdint>

#define BB 32
#define SS 4096
#define DD 64
#define KCC 256

// ------------------------- device global scratch ---------------------------
__device__ __half g_Wh[2 * KCC * SS];        // [proj][kc][s] fp16
__device__ float  g_acc[2 * BB * KCC * DD];  // [proj][b][kc][d] fp32 partials
                                             // (zero at load; finalize re-zeroes)
__device__ __half g_Ke16[BB * KCC * DD];     // [b][kc][d] fp16 (Ke^T + bias)
__device__ __half g_Vf16[BB * KCC * DD];     // [b][kc][d] fp16 (Vf + bias)

// ------------------------------ helpers ------------------------------------
__device__ __forceinline__ uint32_t smem_u32(const void* p) {
    uint32_t a;
    asm("{ .reg .u64 t; cvta.to.shared.u64 t, %1; cvt.u32.u64 %0, t; }"
        : "=r"(a) : "l"(p));
    return a;
}
#define SW128(x) ((x) ^ (((x) >> 3) & 0x70))

__device__ __forceinline__ void cp16(uint32_t dst, const void* src) {
    asm volatile("cp.async.cg.shared.global [%0], [%1], 16;"
                 :: "r"(dst), "l"(src) : "memory");
}
__device__ __forceinline__ void cp_commit() {
    asm volatile("cp.async.commit_group;" ::: "memory");
}
template <int N>
__device__ __forceinline__ void cp_wait() {
    asm volatile("cp.async.wait_group %0;" :: "n"(N) : "memory");
}
__device__ __forceinline__ void ldm_x4(uint32_t* r, uint32_t addr) {
    asm volatile("ldmatrix.sync.aligned.m8n8.x4.shared.b16 {%0,%1,%2,%3}, [%4];"
                 : "=r"(r[0]), "=r"(r[1]), "=r"(r[2]), "=r"(r[3]) : "r"(addr));
}
__device__ __forceinline__ void ldm_x4_t(uint32_t* r, uint32_t addr) {
    asm volatile("ldmatrix.sync.aligned.m8n8.x4.trans.shared.b16 {%0,%1,%2,%3}, [%4];"
                 : "=r"(r[0]), "=r"(r[1]), "=r"(r[2]), "=r"(r[3]) : "r"(addr));
}
__device__ __forceinline__ void mma_f16(
    float* c, const uint32_t* a, uint32_t b0, uint32_t b1) {
    asm volatile(
        "mma.sync.aligned.m16n8k16.row.col.f32.f16.f16.f32 "
        "{%0,%1,%2,%3}, {%4,%5,%6,%7}, {%8,%9}, {%0,%1,%2,%3};"
        : "+f"(c[0]), "+f"(c[1]), "+f"(c[2]), "+f"(c[3])
        : "r"(a[0]), "r"(a[1]), "r"(a[2]), "r"(a[3]), "r"(b0), "r"(b1));
}
__device__ __forceinline__ uint32_t packhf(float lo, float hi) {
    uint32_t r;
    asm("cvt.rn.f16x2.f32 %0, %1, %2;" : "=r"(r) : "f"(hi), "f"(lo));
    return r;
}
__device__ __forceinline__ float hfres(float v) {   // v - fp16(v)
    return v - __half2float(__float2half(v));
}

// ---------------------------------------------------------------------------
// conv_w: E_w / F_w (fp32 [256][4096]) -> fp16. Grid (256, 2); 4 float4/thr.
// ---------------------------------------------------------------------------
__global__ __launch_bounds__(256) void conv_w_kernel(
    const float* __restrict__ Ew, const float* __restrict__ Fw)
{
    const int y = blockIdx.y;
    const float4* src = reinterpret_cast<const float4*>(y ? Fw : Ew);
    __half2* dst = reinterpret_cast<__half2*>(g_Wh + (size_t)y * KCC * SS);
#pragma unroll
    for (int t = 0; t < 4; t++) {
        const int i = (blockIdx.x * 4 + t) * 256 + threadIdx.x;
        float4 v = src[i];
        dst[2 * i]     = __halves2half2(__float2half(v.x), __float2half(v.y));
        dst[2 * i + 1] = __halves2half2(__float2half(v.z), __float2half(v.w));
    }
}

// ---------------------------------------------------------------------------
// proj_mma: mma.sync fp16 GEMM; s-quarter split + 2 batches per CTA.
// Grid (4, 16, 2) = 128 CTAs. Block 256. One sync per chunk.
// PDL: chunk-0 X loads issued BEFORE cudaGridDependencySynchronize (X is
// independent of conv_w); W loads after.
// SMEM: W 3x32KB @0 | Xf 3x32KB @98304 | Xh 2x16KB @196608 = 224 KB.
// ---------------------------------------------------------------------------
__global__ __launch_bounds__(256) void proj_mma_kernel(
    const float* __restrict__ Kf, const float* __restrict__ Vf)
{
    extern __shared__ char sm[];
    const uint32_t smb = smem_u32(sm);
    const int tid = threadIdx.x, wid = tid >> 5, lane = tid & 31;
    const int sq = blockIdx.x, bp = blockIdx.y, proj = blockIdx.z;
    const int mw = wid >> 2, nw = wid & 3;
    const int g = lane >> 2, q = lane & 3;

    const __half* Wh = g_Wh + (size_t)proj * KCC * SS;
    const float* Xsrc = proj ? Vf : Kf;
    const float* Xb[2] = { Xsrc + (size_t)(2 * bp) * SS * DD,
                           Xsrc + (size_t)(2 * bp + 1) * SS * DD };
    const int sbase = sq * 1024;

    float acc[2][8][2][4];
#pragma unroll
    for (int bb = 0; bb < 2; bb++)
#pragma unroll
        for (int mf = 0; mf < 8; mf++)
#pragma unroll
            for (int nf = 0; nf < 2; nf++)
#pragma unroll
                for (int i = 0; i < 4; i++) acc[bb][mf][nf][i] = 0.f;

    const int NC = 1024 / 64;   // 16 chunks

    auto issue_x = [&](int c) {
        const uint32_t xfbuf = smb + 98304 + (c % 3) * 32768;
#pragma unroll
        for (int bb = 0; bb < 2; bb++) {
            const float* xsrc = Xb[bb] + (size_t)(sbase + c * 64) * DD;
#pragma unroll
            for (int u = 0; u < 2; u++) {
                int seg = tid + u * 256;
                cp16(xfbuf + bb * 16384 + seg * 32,      xsrc + seg * 8);
                cp16(xfbuf + bb * 16384 + seg * 32 + 16, xsrc + seg * 8 + 4);
            }
        }
    };
    auto issue_w = [&](int c) {
        const uint32_t wbuf = smb + (c % 3) * 32768;
#pragma unroll
        for (int idx = tid; idx < 2048; idx += 256) {
            int row = idx >> 3, s16 = idx & 7;
            size_t so = (size_t)row * SS + sbase + c * 64 + s16 * 8;
            uint32_t bo = SW128((uint32_t)(row * 128 + s16 * 16));
            cp16(wbuf + bo, Wh + so);
        }
    };
    auto load_chunk = [&](int c) { issue_x(c); issue_w(c); cp_commit(); };

    auto convert_x = [&](int c) {
        const char* xf = sm + 98304 + (c % 3) * 32768;
        char* xbb = sm + 196608 + (c & 1) * 16384;
#pragma unroll
        for (int bb = 0; bb < 2; bb++)
#pragma unroll
            for (int u = 0; u < 2; u++) {
                int seg = tid + u * 256;
                int row = seg >> 3, s16 = seg & 7;
                float4 v0 = *reinterpret_cast<const float4*>(
                    xf + bb * 16384 + seg * 32);
                float4 v1 = *reinterpret_cast<const float4*>(
                    xf + bb * 16384 + seg * 32 + 16);
                uint32_t bo = SW128((uint32_t)(row * 128 + s16 * 16));
                uint4 h;
                h.x = packhf(v0.x, v0.y); h.y = packhf(v0.z, v0.w);
                h.z = packhf(v1.x, v1.y); h.w = packhf(v1.z, v1.w);
                *reinterpret_cast<uint4*>(xbb + bb * 8192 + bo) = h;
            }
    };

    // PDL: X loads are independent of conv_w; W must wait.
    issue_x(0);
    cudaGridDependencySynchronize();
    issue_w(0); cp_commit();
    load_chunk(1);

    for (int c = 0; c < NC; c++) {
        cp_wait<1>();
        convert_x(c);
        __syncthreads();
        if (c + 2 < NC) load_chunk(c + 2);

        const uint32_t Ah = smb + (c % 3) * 32768;
        const uint32_t Xh = smb + 196608 + (c & 1) * 16384;
        const int lr = lane & 15, lc = (lane >> 4) * 16;

#pragma unroll
        for (int kk = 0; kk < 4; kk++) {
            uint32_t bh[2][4];
            uint32_t boff = SW128((uint32_t)((kk * 16 + lr) * 128 + nw * 32 + lc));
            ldm_x4_t(bh[0], Xh + boff);
            ldm_x4_t(bh[1], Xh + 8192 + boff);
#pragma unroll
            for (int mf = 0; mf < 8; mf++) {
                uint32_t ah[4];
                uint32_t off = SW128((uint32_t)(
                    (mw * 128 + mf * 16 + lr) * 128 + kk * 32 + lc));
                ldm_x4(ah, Ah + off);
#pragma unroll
                for (int bb = 0; bb < 2; bb++)
#pragma unroll
                    for (int nf = 0; nf < 2; nf++)
                        mma_f16(acc[bb][mf][nf], ah,
                                bh[bb][2 * nf], bh[bb][2 * nf + 1]);
            }
        }
    }

    // ---- epilogue: vector float2 atomics into g_acc ----
#pragma unroll
    for (int bb = 0; bb < 2; bb++) {
        float* out = g_acc + ((size_t)proj * BB + 2 * bp + bb) * KCC * DD;
#pragma unroll
        for (int mf = 0; mf < 8; mf++) {
            const int kcl = mw * 128 + mf * 16 + g;
#pragma unroll
            for (int nf = 0; nf < 2; nf++) {
                const int d0 = nw * 16 + nf * 8 + 2 * q;
                atomicAdd(reinterpret_cast<float2*>(&out[(size_t)kcl * DD + d0]),
                          make_float2(acc[bb][mf][nf][0], acc[bb][mf][nf][1]));
                atomicAdd(reinterpret_cast<float2*>(&out[(size_t)(kcl + 8) * DD + d0]),
                          make_float2(acc[bb][mf][nf][2], acc[bb][mf][nf][3]));
            }
        }
    }
}

// ---------------------------------------------------------------------------
// finalize: g_acc (+bias) -> fp16 arrays; re-zeroes g_acc (replaces memset).
// Grid (BB*4, 2). Block 256. PDL: waits on proj at entry.
// ---------------------------------------------------------------------------
__global__ __launch_bounds__(256) void finalize_kernel(
    const float* __restrict__ E_b, const float* __restrict__ F_b)
{
    cudaGridDependencySynchronize();

    const int blk = blockIdx.x, proj = blockIdx.y;
    const int b = blk >> 2, quarter = blk & 3;
    float* src = g_acc + ((size_t)proj * BB + b) * KCC * DD;
    const float* bias = proj ? F_b : E_b;
    __half* oh = (proj ? g_Vf16 : g_Ke16) + (size_t)b * KCC * DD;

    const int i0 = quarter * 1024;
    const float4 z = make_float4(0.f, 0.f, 0.f, 0.f);
#pragma unroll
    for (int t = 0; t < 4; t++) {
        const int i = i0 + t * 256 + threadIdx.x;
        const int kc = (i * 4) >> 6;
        const float bv = bias[kc];
        float4 v = reinterpret_cast<const float4*>(src)[i];
        uint2 h;
        h.x = packhf(v.x + bv, v.y + bv);
        h.y = packhf(v.z + bv, v.w + bv);
        reinterpret_cast<uint2*>(oh)[i] = h;
        reinterpret_cast<float4*>(src)[i] = z;   // re-zero for next replay
    }
}

// ---------------------------------------------------------------------------
// attn: fp16 tensor-core attention (rows 0..255) + fused broadcast.
// Grid (8, B) = 256 blocks. Block 128 (4 warps): warps 0-1 do MMA.
// PDL: Q conversion happens BEFORE cudaGridDependencySynchronize.
// SMEM: Ke 32K | Vf 32K | Qh 4K | Ql 4K = 72KB.
// ---------------------------------------------------------------------------
__global__ __launch_bounds__(128) void attn_kernel(
    const float* __restrict__ Qf, float* __restrict__ out)
{
    extern __shared__ char sm[];
    const uint32_t smb = smem_u32(sm);
    const uint32_t KE = 0, VF = 32768, QH = 65536, QL = 69632;

    const int tid = threadIdx.x, lane = tid & 31, warp = tid >> 5;
    const int b = blockIdx.y;
    const int s0 = blockIdx.x * 32;
    const int g = lane >> 2, q = lane & 3;
    const int lr = lane & 15, lcb = (lane >> 4) * 16;

    // ---- Q: fp32 -> fp16 hi/lo smem (independent of finalize) ----
    {
        const float* qb = Qf + ((size_t)b * SS + s0) * DD;
#pragma unroll
        for (int idx = tid; idx < 256; idx += 128) {
            int row = idx >> 3, seg = idx & 7;
            const float* qp = qb + (size_t)row * DD + seg * 8;
            float4 v0 = *reinterpret_cast<const float4*>(qp);
            float4 v1 = *reinterpret_cast<const float4*>(qp + 4);
            uint32_t bo = SW128((uint32_t)(row * 128 + seg * 16));
            uint4 h, l;
            h.x = packhf(v0.x, v0.y); h.y = packhf(v0.z, v0.w);
            h.z = packhf(v1.x, v1.y); h.w = packhf(v1.z, v1.w);
            l.x = packhf(hfres(v0.x), hfres(v0.y));
            l.y = packhf(hfres(v0.z), hfres(v0.w));
            l.z = packhf(hfres(v1.x), hfres(v1.y));
            l.w = packhf(hfres(v1.z), hfres(v1.w));
            *reinterpret_cast<uint4*>(sm + QH + bo) = h;
            *reinterpret_cast<uint4*>(sm + QL + bo) = l;
        }
    }

    cudaGridDependencySynchronize();

    // ---- Ke / Vf fp16 tiles via cp.async ----
    {
        const __half* ke = g_Ke16 + (size_t)b * KCC * DD;
        const __half* vf = g_Vf16 + (size_t)b * KCC * DD;
#pragma unroll
        for (int idx = tid; idx < 2048; idx += 128) {
            int row = idx >> 3, seg = idx & 7;
            size_t so = (size_t)row * DD + seg * 8;
            uint32_t bo = SW128((uint32_t)(row * 128 + seg * 16));
            cp16(smb + KE + bo, ke + so);
            cp16(smb + VF + bo, vf + so);
        }
        cp_commit();
        cp_wait<0>();
        __syncthreads();
    }

    if (warp < 2) {
        const int j0 = blockIdx.x * 2 + warp;   // first unmasked kc tile

        float acc[32][4];
#pragma unroll
        for (int nf = 0; nf < 32; nf++)
#pragma unroll
            for (int i = 0; i < 4; i++) acc[nf][i] = 0.f;

#pragma unroll
        for (int kk = 0; kk < 4; kk++) {
            uint32_t qh[4], ql[4];
            uint32_t offA = SW128((uint32_t)((warp * 16 + lr) * 128 + kk * 32 + lcb));
            ldm_x4(qh, smb + QH + offA);
            ldm_x4(ql, smb + QL + offA);
#pragma unroll
            for (int j = 0; j < 16; j++) {
                if (j >= j0) {
                    uint32_t off = SW128((uint32_t)((j * 16 + lr) * 128 + kk * 32 + lcb));
                    uint32_t bh[4];
                    ldm_x4(bh, smb + KE + off);
                    mma_f16(acc[2 * j],     qh, bh[0], bh[2]);
                    mma_f16(acc[2 * j],     ql, bh[0], bh[2]);
                    mma_f16(acc[2 * j + 1], qh, bh[1], bh[3]);
                    mma_f16(acc[2 * j + 1], ql, bh[1], bh[3]);
                }
            }
        }

        const int rowa = s0 + warp * 16 + g;
        const int rowb = rowa + 8;
        float mxa = -3.4e38f, mxb = -3.4e38f;
#pragma unroll
        for (int nf = 0; nf < 32; nf++) {
            const int kc = 8 * nf + 2 * q;
            acc[nf][0] = (kc     >= rowa) ? acc[nf][0] * 0.125f : -1e10f;
            acc[nf][1] = (kc + 1 >= rowa) ? acc[nf][1] * 0.125f : -1e10f;
            acc[nf][2] = (kc     >= rowb) ? acc[nf][2] * 0.125f : -1e10f;
            acc[nf][3] = (kc + 1 >= rowb) ? acc[nf][3] * 0.125f : -1e10f;
            mxa = fmaxf(mxa, fmaxf(acc[nf][0], acc[nf][1]));
            mxb = fmaxf(mxb, fmaxf(acc[nf][2], acc[nf][3]));
        }
#pragma unroll
        for (int o = 1; o <= 2; o <<= 1) {
            mxa = fmaxf(mxa, __shfl_xor_sync(0xffffffffu, mxa, o));
            mxb = fmaxf(mxb, __shfl_xor_sync(0xffffffffu, mxb, o));
        }
        float sa = 0.f, sb = 0.f;
#pragma unroll
        for (int nf = 0; nf < 32; nf++) {
            acc[nf][0] = __expf(acc[nf][0] - mxa);
            acc[nf][1] = __expf(acc[nf][1] - mxa);
            acc[nf][2] = __expf(acc[nf][2] - mxb);
            acc[nf][3] = __expf(acc[nf][3] - mxb);
            sa += acc[nf][0] + acc[nf][1];
            sb += acc[nf][2] + acc[nf][3];
        }
#pragma unroll
        for (int o = 1; o <= 2; o <<= 1) {
            sa += __shfl_xor_sync(0xffffffffu, sa, o);
            sb += __shfl_xor_sync(0xffffffffu, sb, o);
        }
        const float inva = 1.f / sa, invb = 1.f / sb;

        uint32_t pAh[32], pAl[32], pBh[32], pBl[32];
#pragma unroll
        for (int nf = 0; nf < 32; nf++) {
            float p0 = acc[nf][0] * inva, p1 = acc[nf][1] * inva;
            float p2 = acc[nf][2] * invb, p3 = acc[nf][3] * invb;
            pAh[nf] = packhf(p0, p1);
            pBh[nf] = packhf(p2, p3);
            pAl[nf] = packhf(hfres(p0), hfres(p1));
            pBl[nf] = packhf(hfres(p2), hfres(p3));
        }

        float acc2[8][4];
#pragma unroll
        for (int u = 0; u < 8; u++)
#pragma unroll
            for (int i = 0; i < 4; i++) acc2[u][i] = 0.f;

#pragma unroll
        for (int ks = 0; ks < 16; ks++) {
            if (ks >= j0) {
                uint32_t a_h[4] = {pAh[2 * ks], pBh[2 * ks],
                                   pAh[2 * ks + 1], pBh[2 * ks + 1]};
                uint32_t a_l[4] = {pAl[2 * ks], pBl[2 * ks],
                                   pAl[2 * ks + 1], pBl[2 * ks + 1]};
#pragma unroll
                for (int t = 0; t < 4; t++) {
                    uint32_t off = SW128((uint32_t)((ks * 16 + lr) * 128 + t * 32 + lcb));
                    uint32_t vh[4];
                    ldm_x4_t(vh, smb + VF + off);
                    mma_f16(acc2[2 * t],     a_h, vh[0], vh[1]);
                    mma_f16(acc2[2 * t],     a_l, vh[0], vh[1]);
                    mma_f16(acc2[2 * t + 1], a_h, vh[2], vh[3]);
                    mma_f16(acc2[2 * t + 1], a_l, vh[2], vh[3]);
                }
            }
        }

        float* ob = out + (size_t)b * SS * DD;
#pragma unroll
        for (int u = 0; u < 8; u++) {
            const int d0 = 8 * u + 2 * q;
            *reinterpret_cast<float2*>(&ob[(size_t)rowa * DD + d0]) =
                make_float2(acc2[u][0], acc2[u][1]);
            *reinterpret_cast<float2*>(&ob[(size_t)rowb * DD + d0]) =
                make_float2(acc2[u][2], acc2[u][3]);
        }
    }

    // ---- fused broadcast (4 warps): rows >= KC get mean_k Vf[k][:]. ----
    __syncthreads();
    {
        float* red = reinterpret_cast<float*>(sm + QH);          // [4][64]
        float* meanv = reinterpret_cast<float*>(sm + QH) + 256;  // [64]
        const int dp = tid & 31, kq = tid >> 5;
        float m0 = 0.f, m1 = 0.f;
        for (int k = kq * 64; k < kq * 64 + 64; k++) {
            uint32_t off = SW128((uint32_t)(k * 128 + dp * 4));
            uint32_t hw = *reinterpret_cast<const uint32_t*>(sm + VF + off);
            __half2 hv = *reinterpret_cast<__half2*>(&hw);
            m0 += __half2float(hv.x);
            m1 += __half2float(hv.y);
        }
        red[kq * 64 + 2 * dp]     = m0;
        red[kq * 64 + 2 * dp + 1] = m1;
        __syncthreads();
        if (tid < 64)
            meanv[tid] = (red[tid] + red[64 + tid] + red[128 + tid] +
                          red[192 + tid]) * (1.f / 256.f);
        __syncthreads();

        const int ccol = tid & 15, rofs = tid >> 4;
        const float4 val = make_float4(meanv[ccol * 4], meanv[ccol * 4 + 1],
                                       meanv[ccol * 4 + 2], meanv[ccol * 4 + 3]);
        float4* obv = reinterpret_cast<float4*>(out + (size_t)b * SS * DD);
        const int r0b = KCC + blockIdx.x * 480;
#pragma unroll 4
        for (int r = r0b + rofs; r < r0b + 480; r += 8)
            obv[(size_t)r * 16 + ccol] = val;
    }
}

// ---------------------------------------------------------------------------
// Harness entry. Inputs: Q, K, V, E_w, E_b, F_w, F_b. Output f32 [B,S,D].
// PDL chain: conv_w -> proj -> finalize -> attn (programmatic serialization).
// ---------------------------------------------------------------------------
extern "C" void kernel_launch(void* const* d_in, const int* in_sizes, int n_in,
                              void* d_out, int out_size)
{
    (void)in_sizes; (void)n_in; (void)out_size;
    const float* Q   = (const float*)d_in[0];
    const float* K   = (const float*)d_in[1];
    const float* V   = (const float*)d_in[2];
    const float* E_w = (const float*)d_in[3];
    const float* E_b = (const float*)d_in[4];
    const float* F_w = (const float*)d_in[5];
    const float* F_b = (const float*)d_in[6];
    float* out = (float*)d_out;

    const int proj_smem = 229376;   // 224 KB
    const int attn_smem = 73728;    // 72 KB
    cudaFuncSetAttribute(proj_mma_kernel,
                         cudaFuncAttributeMaxDynamicSharedMemorySize, proj_smem);
    cudaFuncSetAttribute(attn_kernel,
                         cudaFuncAttributeMaxDynamicSharedMemorySize, attn_smem);

    cudaLaunchAttribute pdl[1];
    pdl[0].id = cudaLaunchAttributeProgrammaticStreamSerialization;
    pdl[0].val.programmaticStreamSerializationAllowed = 1;

    // conv_w: plain launch
    conv_w_kernel<<<dim3(256, 2), 256>>>(E_w, F_w);

    // proj (PDL)
    {
        cudaLaunchConfig_t cfg = {};
        cfg.gridDim = dim3(4, BB / 2, 2);
        cfg.blockDim = dim3(256, 1, 1);
        cfg.dynamicSmemBytes = proj_smem;
        cfg.stream = 0;
        cfg.attrs = pdl;
        cfg.numAttrs = 1;
        cudaLaunchKernelEx(&cfg, proj_mma_kernel, K, V);
    }
    // finalize (PDL)
    {
        cudaLaunchConfig_t cfg = {};
        cfg.gridDim = dim3(BB * 4, 2);
        cfg.blockDim = dim3(256, 1, 1);
        cfg.dynamicSmemBytes = 0;
        cfg.stream = 0;
        cfg.attrs = pdl;
        cfg.numAttrs = 1;
        cudaLaunchKernelEx(&cfg, finalize_kernel, E_b, F_b);
    }
    // attn (PDL)
    {
        cudaLaunchConfig_t cfg = {};
        cfg.gridDim = dim3(8, BB);
        cfg.blockDim = dim3(128, 1, 1);
        cfg.dynamicSmemBytes = attn_smem;
        cfg.stream = 0;
        cfg.attrs = pdl;
        cfg.numAttrs = 1;
        cudaLaunchKernelEx(&cfg, attn_kernel, Q, out);
    }
}